// round 1
// baseline (speedup 1.0000x reference)
#include <cuda_runtime.h>
#include <cstdint>

// SpikeFP32GELUExact: input [B,S,D,32] float32 pulse bits (MSB first) encoding
// fp32 values; output = same pulse encoding of fp32(GELU_tanh_fp64(x)).
//
// One thread per value: pack 32 bit-floats -> uint32 -> fp32 -> fp64 GELU
// (tanh form, exactly the reference op chain) -> fp32 -> unpack 32 bit-floats.

__global__ __launch_bounds__(256) void gelu_pulse_kernel(
    const float4* __restrict__ in, float4* __restrict__ out, int n_vals)
{
    int v = blockIdx.x * blockDim.x + threadIdx.x;
    if (v >= n_vals) return;

    // ---- pack: 32 consecutive pulse floats (MSB first) -> uint32 ----
    const float4* pin = in + (size_t)v * 8;
    uint32_t u = 0u;
#pragma unroll
    for (int j = 0; j < 8; ++j) {
        float4 b = pin[j];
        uint32_t nib = ((b.x != 0.0f) ? 8u : 0u)
                     | ((b.y != 0.0f) ? 4u : 0u)
                     | ((b.z != 0.0f) ? 2u : 0u)
                     | ((b.w != 0.0f) ? 1u : 0u);
        u = (u << 4) | nib;
    }

    // ---- exact FP64 GELU chain (matches the reference op-by-op) ----
    float xf = __uint_as_float(u);
    double x  = (double)xf;                       // exact widen
    double x2 = x * x;
    double x3 = x2 * x;
    double inner = x + 0.044715 * x3;
    double z  = 0.7978845608028654 * inner;
    double e2z = exp(2.0 * z);
    double t  = (e2z - 1.0) / (e2z + 1.0);
    double res = 0.5 * (x * (1.0 + t));
    float rf = (float)res;                        // round-to-nearest down-cast
    uint32_t w = __float_as_uint(rf);

    // ---- unpack: uint32 -> 32 pulse floats (MSB first) ----
    float4* pout = out + (size_t)v * 8;
#pragma unroll
    for (int j = 0; j < 8; ++j) {
        uint32_t nib = w >> (28 - 4 * j);
        float4 o;
        o.x = (nib & 8u) ? 1.0f : 0.0f;
        o.y = (nib & 4u) ? 1.0f : 0.0f;
        o.z = (nib & 2u) ? 1.0f : 0.0f;
        o.w = (nib & 1u) ? 1.0f : 0.0f;
        pout[j] = o;
    }
}

extern "C" void kernel_launch(void* const* d_in, const int* in_sizes, int n_in,
                              void* d_out, int out_size)
{
    const float4* in = (const float4*)d_in[0];
    float4* out = (float4*)d_out;
    int n_vals = in_sizes[0] / 32;            // 32 pulse floats per value
    int threads = 256;
    int blocks = (n_vals + threads - 1) / threads;
    gelu_pulse_kernel<<<blocks, threads>>>(in, out, n_vals);
}

// round 2
// speedup vs baseline: 1.0089x; 1.0089x over previous
#include <cuda_runtime.h>
#include <cstdint>

// SpikeFP32GELUExact: input [B,S,D,32] float32 pulse bits (MSB first) encoding
// fp32 values; output = same pulse encoding of fp32(GELU_tanh_fp64(x)).
//
// Warp-cooperative layout: one warp owns 32 consecutive values = 1024
// contiguous floats. Iteration t: lane l loads float t*32+l (coalesced, one
// 128B line per LDG), which is pulse-bit l of value t. __ballot_sync packs
// the word; __brev converts MSB-first pulse order to the uint32 bit pattern.
// Each lane then runs the exact fp64 GELU chain on its own value. Output is
// the mirror: shfl word t to all lanes, lane l stores bit l (coalesced STG).

__global__ __launch_bounds__(256) void gelu_pulse_kernel(
    const float* __restrict__ in, float* __restrict__ out, int n_vals)
{
    const unsigned FULL = 0xFFFFFFFFu;
    int gwarp = (int)((blockIdx.x * blockDim.x + threadIdx.x) >> 5);
    int lane  = threadIdx.x & 31;
    if (gwarp * 32 >= n_vals) return;

    size_t base = (size_t)gwarp * 1024;   // 32 values * 32 bits
    const float* p = in + base + lane;

    // ---- coalesced load + ballot pack ----
    uint32_t my_u = 0;
#pragma unroll
    for (int t = 0; t < 32; ++t) {
        float f = p[(size_t)t * 32];
        uint32_t b = __ballot_sync(FULL, f != 0.0f);  // bit l = pulse bit l of value t
        if (lane == t) my_u = b;
    }
    my_u = __brev(my_u);  // pulse bit i has significance 31-i

    // ---- exact FP64 GELU chain (matches the reference op-by-op) ----
    float  xf = __uint_as_float(my_u);
    double x  = (double)xf;                     // exact widen
    double x2 = x * x;
    double x3 = x2 * x;
    double inner = x + 0.044715 * x3;
    double z  = 0.7978845608028654 * inner;
    double e2z = exp(2.0 * z);
    double t_ = (e2z - 1.0) / (e2z + 1.0);
    double res = 0.5 * (x * (1.0 + t_));
    float  rf = (float)res;                     // round-to-nearest down-cast
    uint32_t w = __brev(__float_as_uint(rf));   // bit l of w = pulse bit l

    // ---- coalesced store via shfl broadcast ----
    float* q = out + base + lane;
#pragma unroll
    for (int t = 0; t < 32; ++t) {
        uint32_t wt = __shfl_sync(FULL, w, t);
        q[(size_t)t * 32] = __uint_as_float(((wt >> lane) & 1u) * 0x3F800000u);
    }
}

extern "C" void kernel_launch(void* const* d_in, const int* in_sizes, int n_in,
                              void* d_out, int out_size)
{
    const float* in = (const float*)d_in[0];
    float* out = (float*)d_out;
    int n_vals = in_sizes[0] / 32;   // 32 pulse floats per value
    int threads = 256;               // 8 warps/block, each warp does 32 values
    int warps = (n_vals + 31) / 32;
    int blocks = (warps * 32 + threads - 1) / threads;
    gelu_pulse_kernel<<<blocks, threads>>>(in, out, n_vals);
}